// round 4
// baseline (speedup 1.0000x reference)
#include <cuda_runtime.h>

// ---------------------------------------------------------------------------
// Impatient Reader: ctx = fc1(context)+fc2(image); ctx_dm = dm(ctx);
// recurrence over 32 question tokens (attention over S=256 ctx positions);
// g = rg(r) + qg(qh).
// Shapes: S_c=256, S_q=32, B=32, D=512.
// ---------------------------------------------------------------------------

#define D   512
#define NB  32
#define SC  256
#define SQ  32

// scratch (static device allocations; cudaMalloc is forbidden)
__device__ float g_ctx  [NB * SC * D];   // [b][s][e] 16.8 MB
__device__ float g_ctxdm[NB * SC * D];   // 16.8 MB
__device__ float g_qm   [SQ * NB * D];   // [t][b][e] 2.1 MB
__device__ float g_r    [NB * D];
__device__ float g_tr   [NB * D];
__device__ float g_rm   [NB * D];
__device__ float g_logits[NB * SC];

typedef unsigned long long u64;

__device__ __forceinline__ u64 ffma2(u64 a, u64 b, u64 c) {
    u64 d_;
    asm("fma.rn.f32x2 %0, %1, %2, %3;" : "=l"(d_) : "l"(a), "l"(b), "l"(c));
    return d_;
}
__device__ __forceinline__ u64 pack2(float x, float y) {
    u64 d_;
    asm("mov.b64 %0, {%1, %2};" : "=l"(d_) : "f"(x), "f"(y));
    return d_;
}
__device__ __forceinline__ float2 unpack2(u64 v) {
    float2 f;
    asm("mov.b64 {%0, %1}, %2;" : "=f"(f.x), "=f"(f.y) : "l"(v));
    return f;
}
__device__ __forceinline__ float tanh_fast(float x) {
    float y;
    asm("tanh.approx.f32 %0, %1;" : "=f"(y) : "f"(x));
    return y;
}

// ---------------------------------------------------------------------------
// Big GEMM: C[M,512] = sum over phases of A_ph @ W_ph  (+ biases)
// BM=128, BN=128, BK=8, 256 threads, 8x8 per thread, packed f32x2 FMA.
// AMODE 0: A row-major [m][k] (lda=512).
// AMODE 1: m = b*256+s, A element at s*(32*512) + b*512 + k (seq-first input).
// M must be a multiple of 128, N = 512.
// ---------------------------------------------------------------------------
template <int NPH, int AMODE>
__global__ __launch_bounds__(256) void sgemm_kernel(
    const float* __restrict__ A0, const float* __restrict__ W0, const float* __restrict__ bias0,
    const float* __restrict__ A1, const float* __restrict__ W1, const float* __restrict__ bias1,
    float* __restrict__ C)
{
    __shared__ float As[8][128];
    __shared__ float Bs[8][132];

    const int tid = threadIdx.x;
    const int tx = tid & 15, ty = tid >> 4;
    const int bx = blockIdx.x, by = blockIdx.y;

    const int arow = tid >> 1;          // 0..127
    const int acol = (tid & 1) * 4;     // 0 or 4
    const int m    = by * 128 + arow;
    long aoff;
    if (AMODE == 1) {
        int s = m & 255, b = m >> 8;
        aoff = (long)s * (NB * D) + (long)b * D;
    } else {
        aoff = (long)m * D;
    }

    const int brow = tid >> 5;          // 0..7
    const int bcol = (tid & 31) * 4;    // 0..124
    const int wcol = bx * 128 + bcol;

    u64 acc[8][4];
#pragma unroll
    for (int i = 0; i < 8; i++)
#pragma unroll
        for (int j = 0; j < 4; j++) acc[i][j] = 0ull;

    const int KK = NPH * D;

    // software-pipelined global loads
    float4 av, bv;
    {
        const float* A = A0;
        const float* W = W0;
        av = *(const float4*)&A[aoff + 0 + acol];
        bv = *(const float4*)&W[(long)(0 + brow) * D + wcol];
    }

    for (int kk = 0; kk < KK; kk += 8) {
        As[acol + 0][arow] = av.x;
        As[acol + 1][arow] = av.y;
        As[acol + 2][arow] = av.z;
        As[acol + 3][arow] = av.w;
        *(float4*)&Bs[brow][bcol] = bv;
        __syncthreads();

        int kn = kk + 8;
        if (kn < KK) {
            int ph = kn >> 9;
            int k  = kn & 511;
            const float* A = (NPH == 2 && ph == 1) ? A1 : A0;
            const float* W = (NPH == 2 && ph == 1) ? W1 : W0;
            av = *(const float4*)&A[aoff + k + acol];
            bv = *(const float4*)&W[(long)(k + brow) * D + wcol];
        }

#pragma unroll
        for (int k = 0; k < 8; k++) {
            float4 a0 = *(float4*)&As[k][ty * 8];
            float4 a1 = *(float4*)&As[k][ty * 8 + 4];
            u64 b0 = *(u64*)&Bs[k][tx * 8 + 0];
            u64 b1 = *(u64*)&Bs[k][tx * 8 + 2];
            u64 b2 = *(u64*)&Bs[k][tx * 8 + 4];
            u64 b3 = *(u64*)&Bs[k][tx * 8 + 6];
            float a[8] = {a0.x, a0.y, a0.z, a0.w, a1.x, a1.y, a1.z, a1.w};
#pragma unroll
            for (int i = 0; i < 8; i++) {
                u64 ai = pack2(a[i], a[i]);
                acc[i][0] = ffma2(ai, b0, acc[i][0]);
                acc[i][1] = ffma2(ai, b1, acc[i][1]);
                acc[i][2] = ffma2(ai, b2, acc[i][2]);
                acc[i][3] = ffma2(ai, b3, acc[i][3]);
            }
        }
        __syncthreads();
    }

    // epilogue: bias add + store
    const int n0 = bx * 128 + tx * 8;
    float bb[8];
#pragma unroll
    for (int j = 0; j < 8; j++) {
        bb[j] = bias0[n0 + j];
        if (NPH == 2) bb[j] += bias1[n0 + j];
    }
#pragma unroll
    for (int i = 0; i < 8; i++) {
        int row = by * 128 + ty * 8 + i;
        float o[8];
#pragma unroll
        for (int j = 0; j < 4; j++) {
            float2 v = unpack2(acc[i][j]);
            o[2 * j]     = v.x + bb[2 * j];
            o[2 * j + 1] = v.y + bb[2 * j + 1];
        }
        *(float4*)&C[(long)row * D + n0]     = make_float4(o[0], o[1], o[2], o[3]);
        *(float4*)&C[(long)row * D + n0 + 4] = make_float4(o[4], o[5], o[6], o[7]);
    }
}

// ---------------------------------------------------------------------------
// Small [32,512] = A[32,512] @ W[512,512] + b  (two weight sets per launch).
// grid (32 col-tiles of 16, 2 matrices, 2 b-halves), 128 threads.
// mat==1 optionally applies tanh (for the rr path).
// ---------------------------------------------------------------------------
__global__ __launch_bounds__(128) void small_linear_kernel(
    const float* __restrict__ A,
    const float* __restrict__ W0, const float* __restrict__ b0v,
    const float* __restrict__ W1, const float* __restrict__ b1v,
    float* __restrict__ O0, float* __restrict__ O1, int tanh1)
{
    __shared__ float As[16][68];
    __shared__ float Ws[64][20];

    const int mat = blockIdx.y;
    const float* W    = mat ? W1 : W0;
    const float* bias = mat ? b1v : b0v;
    float* O          = mat ? O1 : O0;

    const int ct = blockIdx.x * 16;
    const int bh = blockIdx.z * 16;
    const int tid = threadIdx.x;
    const int row = tid >> 3, cp = tid & 7;
    const int koff = (tid & 7) * 8;
    const int wk = tid >> 1, wq = (tid & 1) * 8;

    u64 acc = 0ull;

    for (int kt = 0; kt < D; kt += 64) {
        float4 a0 = *(const float4*)&A[(bh + row) * D + kt + koff];
        float4 a1 = *(const float4*)&A[(bh + row) * D + kt + koff + 4];
        *(float4*)&As[row][koff]     = a0;
        *(float4*)&As[row][koff + 4] = a1;
        float4 w0 = *(const float4*)&W[(long)(kt + wk) * D + ct + wq];
        float4 w1 = *(const float4*)&W[(long)(kt + wk) * D + ct + wq + 4];
        *(float4*)&Ws[wk][wq]     = w0;
        *(float4*)&Ws[wk][wq + 4] = w1;
        __syncthreads();
#pragma unroll
        for (int k = 0; k < 64; k++) {
            float a = As[row][k];
            u64 wv = *(const u64*)&Ws[k][cp * 2];
            acc = ffma2(pack2(a, a), wv, acc);
        }
        __syncthreads();
    }

    float2 v = unpack2(acc);
    v.x += bias[ct + cp * 2];
    v.y += bias[ct + cp * 2 + 1];
    if (tanh1 && mat == 1) { v.x = tanhf(v.x); v.y = tanhf(v.y); }
    *(float2*)&O[(bh + row) * D + ct + cp * 2] = v;
}

// ---------------------------------------------------------------------------
// Final: out[32,512] = r@W_rg + b_rg + qh@W_qg + b_qg
// grid (32 col-tiles, 2 b-halves), 128 threads.
// ---------------------------------------------------------------------------
__global__ __launch_bounds__(128) void final_kernel(
    const float* __restrict__ rA, const float* __restrict__ Wrg, const float* __restrict__ brg,
    const float* __restrict__ qh, const float* __restrict__ Wqg, const float* __restrict__ bqg,
    float* __restrict__ out)
{
    __shared__ float As[16][68];
    __shared__ float Ws[64][20];

    const int ct = blockIdx.x * 16;
    const int bh = blockIdx.y * 16;
    const int tid = threadIdx.x;
    const int row = tid >> 3, cp = tid & 7;
    const int koff = (tid & 7) * 8;
    const int wk = tid >> 1, wq = (tid & 1) * 8;

    u64 acc = 0ull;

    for (int ph = 0; ph < 2; ph++) {
        const float* A = ph ? qh : rA;
        const float* W = ph ? Wqg : Wrg;
        for (int kt = 0; kt < D; kt += 64) {
            float4 a0 = *(const float4*)&A[(bh + row) * D + kt + koff];
            float4 a1 = *(const float4*)&A[(bh + row) * D + kt + koff + 4];
            *(float4*)&As[row][koff]     = a0;
            *(float4*)&As[row][koff + 4] = a1;
            float4 w0 = *(const float4*)&W[(long)(kt + wk) * D + ct + wq];
            float4 w1 = *(const float4*)&W[(long)(kt + wk) * D + ct + wq + 4];
            *(float4*)&Ws[wk][wq]     = w0;
            *(float4*)&Ws[wk][wq + 4] = w1;
            __syncthreads();
#pragma unroll
            for (int k = 0; k < 64; k++) {
                float a = As[row][k];
                u64 wv = *(const u64*)&Ws[k][cp * 2];
                acc = ffma2(pack2(a, a), wv, acc);
            }
            __syncthreads();
        }
    }

    float2 v = unpack2(acc);
    v.x += brg[ct + cp * 2]     + bqg[ct + cp * 2];
    v.y += brg[ct + cp * 2 + 1] + bqg[ct + cp * 2 + 1];
    *(float2*)&out[(bh + row) * D + ct + cp * 2] = v;
}

// ---------------------------------------------------------------------------
// logits[b,s] = sum_d tanh(ctx_dm[b,s,d] + rm[b,d] + qm[t,b,d]) * W_ms[d] + b_ms
// grid (32 s-tiles of 8, 32 b), 256 threads (8 warps, 1 warp per s-row).
// ---------------------------------------------------------------------------
__global__ __launch_bounds__(256) void logits_kernel(
    const float* __restrict__ qm_t, const float* __restrict__ Wms,
    const float* __restrict__ bms)
{
    __shared__ float addv[D];
    __shared__ float wms[D];

    const int b = blockIdx.y;
    const int tid = threadIdx.x;
    addv[tid]       = g_rm[b * D + tid]       + qm_t[b * D + tid];
    addv[tid + 256] = g_rm[b * D + tid + 256] + qm_t[b * D + tid + 256];
    wms[tid]       = Wms[tid];
    wms[tid + 256] = Wms[tid + 256];
    __syncthreads();

    const int w = tid >> 5, lane = tid & 31;
    const int s = blockIdx.x * 8 + w;
    const float4* row = (const float4*)(g_ctxdm + ((long)b * SC + s) * D);

    float acc = 0.f;
#pragma unroll
    for (int j = 0; j < 4; j++) {
        int i4 = j * 32 + lane;
        float4 v  = row[i4];
        float4 a4 = *(const float4*)&addv[i4 * 4];
        float4 w4 = *(const float4*)&wms[i4 * 4];
        acc += tanh_fast(v.x + a4.x) * w4.x;
        acc += tanh_fast(v.y + a4.y) * w4.y;
        acc += tanh_fast(v.z + a4.z) * w4.z;
        acc += tanh_fast(v.w + a4.w) * w4.w;
    }
#pragma unroll
    for (int off = 16; off; off >>= 1) acc += __shfl_xor_sync(0xffffffffu, acc, off);
    if (lane == 0) g_logits[b * SC + s] = acc + bms[0];
}

// ---------------------------------------------------------------------------
// softmax over s, then r[b,:] = sum_s p[s]*ctx[b,s,:] + tr[b,:]
// grid (32), 256 threads. Deterministic (fixed reduction order).
// ---------------------------------------------------------------------------
__global__ __launch_bounds__(256) void update_kernel()
{
    __shared__ float p[SC];
    __shared__ float red[8];
    __shared__ float red2[8];
    __shared__ float4 partial[128];

    const int b = blockIdx.x, tid = threadIdx.x;

    float l = g_logits[b * SC + tid];
    float m = l;
#pragma unroll
    for (int off = 16; off; off >>= 1) m = fmaxf(m, __shfl_xor_sync(0xffffffffu, m, off));
    if ((tid & 31) == 0) red[tid >> 5] = m;
    __syncthreads();
    float mm = red[0];
#pragma unroll
    for (int i = 1; i < 8; i++) mm = fmaxf(mm, red[i]);

    float e = __expf(l - mm);
    float sZ = e;
#pragma unroll
    for (int off = 16; off; off >>= 1) sZ += __shfl_xor_sync(0xffffffffu, sZ, off);
    if ((tid & 31) == 0) red2[tid >> 5] = sZ;
    __syncthreads();
    float Z = 0.f;
#pragma unroll
    for (int i = 0; i < 8; i++) Z += red2[i];
    p[tid] = e / Z;
    __syncthreads();

    const int half = tid >> 7;       // 0/1: split the s-range across thread halves
    const int c4   = tid & 127;      // float4 column index (covers 512 cols)
    const float4* cb = (const float4*)(g_ctx + (long)b * SC * D);
    const int s0 = half << 7;

    float4 acc = make_float4(0.f, 0.f, 0.f, 0.f);
    for (int ss = 0; ss < 128; ss++) {
        float w = p[s0 + ss];
        float4 v = cb[(long)(s0 + ss) * 128 + c4];
        acc.x += w * v.x; acc.y += w * v.y; acc.z += w * v.z; acc.w += w * v.w;
    }
    if (half == 1) partial[c4] = acc;
    __syncthreads();
    if (half == 0) {
        float4 q = partial[c4];
        float4 t4 = ((const float4*)(g_tr + b * D))[c4];
        float4 o = make_float4(acc.x + q.x + t4.x, acc.y + q.y + t4.y,
                               acc.z + q.z + t4.z, acc.w + q.w + t4.w);
        ((float4*)(g_r + b * D))[c4] = o;
    }
}

__global__ void zero_r_kernel()
{
    int i = blockIdx.x * blockDim.x + threadIdx.x;
    if (i < NB * D) g_r[i] = 0.f;
}

// ---------------------------------------------------------------------------
extern "C" void kernel_launch(void* const* d_in, const int* in_sizes, int n_in,
                              void* d_out, int out_size)
{
    const float* ctx_in = (const float*)d_in[0];   // [256,32,512]
    const float* q_in   = (const float*)d_in[1];   // [32,32,512]
    const float* qh     = (const float*)d_in[2];   // [32,512]
    const float* img_in = (const float*)d_in[3];   // [256,32,512]
    const float* W_fc1 = (const float*)d_in[4];  const float* b_fc1 = (const float*)d_in[5];
    const float* W_fc2 = (const float*)d_in[6];  const float* b_fc2 = (const float*)d_in[7];
    const float* W_dm  = (const float*)d_in[8];  const float* b_dm  = (const float*)d_in[9];
    const float* W_rm  = (const float*)d_in[10]; const float* b_rm  = (const float*)d_in[11];
    const float* W_qm  = (const float*)d_in[12]; const float* b_qm  = (const float*)d_in[13];
    const float* W_rr  = (const float*)d_in[14]; const float* b_rr  = (const float*)d_in[15];
    const float* W_rg  = (const float*)d_in[16]; const float* b_rg  = (const float*)d_in[17];
    const float* W_qg  = (const float*)d_in[18]; const float* b_qg  = (const float*)d_in[19];
    const float* W_ms  = (const float*)d_in[20]; const float* b_ms  = (const float*)d_in[21];
    float* out = (float*)d_out;

    float *ctx, *ctxdm, *qm, *r, *tr, *rm;
    cudaGetSymbolAddress((void**)&ctx,   g_ctx);
    cudaGetSymbolAddress((void**)&ctxdm, g_ctxdm);
    cudaGetSymbolAddress((void**)&qm,    g_qm);
    cudaGetSymbolAddress((void**)&r,     g_r);
    cudaGetSymbolAddress((void**)&tr,    g_tr);
    cudaGetSymbolAddress((void**)&rm,    g_rm);

    zero_r_kernel<<<32, 512>>>();

    // ctx = context@W_fc1 + b_fc1 + image@W_fc2 + b_fc2   ([b][s][e], M=8192)
    sgemm_kernel<2, 1><<<dim3(4, 64), 256>>>(ctx_in, W_fc1, b_fc1, img_in, W_fc2, b_fc2, ctx);
    // ctx_dm = ctx@W_dm + b_dm
    sgemm_kernel<1, 0><<<dim3(4, 64), 256>>>(ctx, W_dm, b_dm, nullptr, nullptr, nullptr, ctxdm);
    // qm[t,b,:] = question[t,b,:]@W_qm + b_qm   (M=1024)
    sgemm_kernel<1, 0><<<dim3(4, 8), 256>>>(q_in, W_qm, b_qm, nullptr, nullptr, nullptr, qm);

    for (int t = 0; t < SQ; t++) {
        // rm = r@W_rm + b_rm ; tr = tanh(r@W_rr + b_rr)
        small_linear_kernel<<<dim3(32, 2, 2), 128>>>(r, W_rm, b_rm, W_rr, b_rr, rm, tr, 1);
        // logits over all (b,s)
        logits_kernel<<<dim3(32, 32), 256>>>(qm + (long)t * NB * D, W_ms, b_ms);
        // softmax + weighted ctx sum + tr  -> new r
        update_kernel<<<32, 256>>>();
    }

    final_kernel<<<dim3(32, 2), 128>>>(r, W_rg, b_rg, qh, W_qg, b_qg, out);
}

// round 6
// speedup vs baseline: 1.4415x; 1.4415x over previous
#include <cuda_runtime.h>

// ---------------------------------------------------------------------------
// Impatient Reader on GB300.  S_c=256, S_q=32, B=32, D=512.
// R4 rewrite: 512-thread f32x2 GEMMs with duplicated-A smem (no pack MOVs in
// the hot loop), qm folded into the dm launch, loop kernels re-parallelized.
// ---------------------------------------------------------------------------

#define D   512
#define NB  32
#define SC  256
#define SQ  32

__device__ float g_ctx  [NB * SC * D];   // [b][s][e]
__device__ float g_ctxdm[NB * SC * D];
__device__ float g_qm   [SQ * NB * D];   // [t][b][e]
__device__ float g_r    [NB * D];
__device__ float g_tr   [NB * D];
__device__ float g_rm   [NB * D];
__device__ float g_logits[NB * SC];

typedef unsigned long long u64;

__device__ __forceinline__ u64 ffma2(u64 a, u64 b, u64 c) {
    u64 d_;
    asm("fma.rn.f32x2 %0, %1, %2, %3;" : "=l"(d_) : "l"(a), "l"(b), "l"(c));
    return d_;
}
__device__ __forceinline__ u64 pack2(float x, float y) {
    u64 d_;
    asm("mov.b64 %0, {%1, %2};" : "=l"(d_) : "f"(x), "f"(y));
    return d_;
}
__device__ __forceinline__ float2 unpack2(u64 v) {
    float2 f;
    asm("mov.b64 {%0, %1}, %2;" : "=f"(f.x), "=f"(f.y) : "l"(v));
    return f;
}
__device__ __forceinline__ float tanh_fast(float x) {
    float y;
    asm("tanh.approx.f32 %0, %1;" : "=f"(y) : "f"(x));
    return y;
}

union F4U {
    float4 f;
    u64 u[2];
};

// ---------------------------------------------------------------------------
// GEMM core: 512 threads, BM=128, BN=128, BK=16, f32x2 FMA.
// Duplicated-A smem: Asd[k][2*row] = Asd[k][2*row+1] = A[row][k], so the
// inner loop reads {a,a} pairs with LDS.128 and does 16 FFMA2 per k with
// ZERO pack/mov instructions.  Two-phase K supported (switch at k=512).
// ---------------------------------------------------------------------------
struct GemmSmem {
    float Asd[16][260];   // 16-byte aligned rows (260*4 = 1040 = 65*16)
    float Bs [16][128];
};

__device__ __forceinline__ void gemm_tile_body(
    GemmSmem& sm,
    const float* __restrict__ A0, const float* __restrict__ A1,
    const float* __restrict__ W0, const float* __restrict__ W1,
    const float* __restrict__ bias0, const float* __restrict__ bias1,
    float* __restrict__ C, int KK, long aoff, int rowbase, int bx)
{
    const int tid  = threadIdx.x;
    const int arow = tid >> 2;           // 0..127
    const int ac4  = (tid & 3) * 4;      // 0,4,8,12
    const int brow = tid >> 5;           // 0..15
    const int bc4  = (tid & 31) * 4;     // 0..124
    const int tx   = tid & 31;           // col-group (4 cols)
    const int tyg  = tid >> 5;           // row-group (8 rows)
    const int wcol = bx * 128 + bc4;

    u64 acc[8][2];
#pragma unroll
    for (int i = 0; i < 8; i++) { acc[i][0] = 0ull; acc[i][1] = 0ull; }

    float4 av, bv;
    av = *(const float4*)&A0[aoff + ac4];
    bv = *(const float4*)&W0[(long)brow * D + wcol];

    for (int kk = 0; kk < KK; kk += 16) {
        // stage current tile
#pragma unroll
        for (int j = 0; j < 4; j++) {
            float v = (&av.x)[j];
            *(u64*)&sm.Asd[ac4 + j][2 * arow] = pack2(v, v);
        }
        *(float4*)&sm.Bs[brow][bc4] = bv;
        __syncthreads();

        // prefetch next tile
        int kn = kk + 16;
        if (kn < KK) {
            const float* A = (kn >= 512) ? A1 : A0;
            const float* W = (kn >= 512) ? W1 : W0;
            int kin = kn & 511;
            av = *(const float4*)&A[aoff + kin + ac4];
            bv = *(const float4*)&W[(long)(kin + brow) * D + wcol];
        }

        // compute
#pragma unroll
        for (int k = 0; k < 16; k++) {
            F4U a0, a1, a2, a3, bq;
            const float* ap = sm.Asd[k] + tyg * 16;
            a0.f = *(const float4*)(ap + 0);
            a1.f = *(const float4*)(ap + 4);
            a2.f = *(const float4*)(ap + 8);
            a3.f = *(const float4*)(ap + 12);
            bq.f = *(const float4*)(sm.Bs[k] + tx * 4);
            u64 b0 = bq.u[0], b1 = bq.u[1];
            u64 ad[8] = {a0.u[0], a0.u[1], a1.u[0], a1.u[1],
                         a2.u[0], a2.u[1], a3.u[0], a3.u[1]};
#pragma unroll
            for (int i = 0; i < 8; i++) {
                acc[i][0] = ffma2(ad[i], b0, acc[i][0]);
                acc[i][1] = ffma2(ad[i], b1, acc[i][1]);
            }
        }
        __syncthreads();
    }

    // epilogue
    const int n0 = bx * 128 + tx * 4;
    float bb[4];
#pragma unroll
    for (int j = 0; j < 4; j++) {
        bb[j] = bias0[n0 + j];
        if (bias1) bb[j] += bias1[n0 + j];
    }
#pragma unroll
    for (int i = 0; i < 8; i++) {
        int row = rowbase + tyg * 8 + i;
        float2 v0 = unpack2(acc[i][0]);
        float2 v1 = unpack2(acc[i][1]);
        *(float4*)&C[(long)row * D + n0] =
            make_float4(v0.x + bb[0], v0.y + bb[1], v1.x + bb[2], v1.y + bb[3]);
    }
}

// fc: ctx[b*256+s] = context@W_fc1 + image@W_fc2 + biases.  A seq-first.
__global__ __launch_bounds__(512) void sgemm_fc_kernel(
    const float* __restrict__ A0, const float* __restrict__ W0, const float* __restrict__ b0,
    const float* __restrict__ A1, const float* __restrict__ W1, const float* __restrict__ b1,
    float* __restrict__ C)
{
    __shared__ GemmSmem sm;
    const int by = blockIdx.y;
    const int arow = threadIdx.x >> 2;
    const int m = by * 128 + arow;
    const int s = m & 255, b = m >> 8;
    long aoff = (long)s * (NB * D) + (long)b * D;
    gemm_tile_body(sm, A0, A1, W0, W1, b0, b1, C, 1024, aoff, by * 128, blockIdx.x);
}

// dual: by<64 -> ctxdm = ctx@W_dm, by>=64 -> qm = q@W_qm.  Both row-major, K=512.
__global__ __launch_bounds__(512) void sgemm_dual_kernel(
    const float* __restrict__ Adm, const float* __restrict__ Wdm, const float* __restrict__ bdm,
    float* __restrict__ Cdm,
    const float* __restrict__ Aq,  const float* __restrict__ Wq,  const float* __restrict__ bq,
    float* __restrict__ Cq)
{
    __shared__ GemmSmem sm;
    const int by = blockIdx.y;
    const bool qm = (by >= 64);
    const float* A    = qm ? Aq  : Adm;
    const float* W    = qm ? Wq  : Wdm;
    const float* bias = qm ? bq  : bdm;
    float* C          = qm ? Cq  : Cdm;
    const int byl = qm ? (by - 64) : by;
    const int arow = threadIdx.x >> 2;
    long aoff = (long)(byl * 128 + arow) * D;
    gemm_tile_body(sm, A, A, W, W, bias, nullptr, C, 512, aoff, byl * 128, blockIdx.x);
}

// ---------------------------------------------------------------------------
// GEMV pair: rm = r@W_rm + b_rm ; tr = tanh(r@W_rr + b_rr).
// grid (32 col-chunks of 16, 2 matrices), 256 threads.
// Duplicated-A smem + f32x2 inner loop (3 instr / 2 flops per k).
// ---------------------------------------------------------------------------
__global__ __launch_bounds__(256) void gemv_kernel(
    const float* __restrict__ A,
    const float* __restrict__ W0, const float* __restrict__ b0v,
    const float* __restrict__ W1, const float* __restrict__ b1v,
    float* __restrict__ O0, float* __restrict__ O1)
{
    __shared__ float Asd[32][130];   // dup pairs for 64 k per chunk
    __shared__ float Ws [64][16];

    const int mat = blockIdx.y;
    const float* W    = mat ? W1 : W0;
    const float* bias = mat ? b1v : b0v;
    float* O          = mat ? O1 : O0;

    const int ct = blockIdx.x * 16;
    const int tid = threadIdx.x;
    const int r  = tid >> 3;        // 0..31
    const int cp = tid & 7;         // col pair
    const int ar  = tid >> 3, ak8 = (tid & 7) * 8;
    const int wr  = tid >> 2, wc4 = (tid & 3) * 4;

    u64 acc = 0ull;

    for (int kt = 0; kt < D; kt += 64) {
        float4 v0 = *(const float4*)&A[ar * D + kt + ak8];
        float4 v1 = *(const float4*)&A[ar * D + kt + ak8 + 4];
#pragma unroll
        for (int j = 0; j < 4; j++) {
            *(u64*)&Asd[ar][2 * (ak8 + j)]     = pack2((&v0.x)[j], (&v0.x)[j]);
            *(u64*)&Asd[ar][2 * (ak8 + 4 + j)] = pack2((&v1.x)[j], (&v1.x)[j]);
        }
        *(float4*)&Ws[wr][wc4] = *(const float4*)&W[(long)(kt + wr) * D + ct + wc4];
        __syncthreads();
#pragma unroll
        for (int k = 0; k < 64; k++) {
            u64 a = *(const u64*)&Asd[r][2 * k];
            u64 w = *(const u64*)&Ws[k][cp * 2];
            acc = ffma2(a, w, acc);
        }
        __syncthreads();
    }

    float2 v = unpack2(acc);
    v.x += bias[ct + cp * 2];
    v.y += bias[ct + cp * 2 + 1];
    if (mat == 1) { v.x = tanhf(v.x); v.y = tanhf(v.y); }
    *(float2*)&O[r * D + ct + cp * 2] = v;
}

// ---------------------------------------------------------------------------
// logits[b,s] = sum_d tanh(ctx_dm[b,s,d] + rm[b,d] + qm[t,b,d]) * W_ms[d] + b_ms
// grid (32 s-tiles of 8, 32 b), 256 threads (warp per s-row).
// ---------------------------------------------------------------------------
__global__ __launch_bounds__(256) void logits_kernel(
    const float* __restrict__ qm_t, const float* __restrict__ Wms,
    const float* __restrict__ bms)
{
    __shared__ float addv[D];
    __shared__ float wms[D];

    const int b = blockIdx.y;
    const int tid = threadIdx.x;
    addv[tid]       = g_rm[b * D + tid]       + qm_t[b * D + tid];
    addv[tid + 256] = g_rm[b * D + tid + 256] + qm_t[b * D + tid + 256];
    wms[tid]       = Wms[tid];
    wms[tid + 256] = Wms[tid + 256];
    __syncthreads();

    const int w = tid >> 5, lane = tid & 31;
    const int s = blockIdx.x * 8 + w;
    const float4* row = (const float4*)(g_ctxdm + ((long)b * SC + s) * D);

    float acc = 0.f;
#pragma unroll
    for (int j = 0; j < 4; j++) {
        int i4 = j * 32 + lane;
        float4 v  = row[i4];
        float4 a4 = *(const float4*)&addv[i4 * 4];
        float4 w4 = *(const float4*)&wms[i4 * 4];
        acc += tanh_fast(v.x + a4.x) * w4.x;
        acc += tanh_fast(v.y + a4.y) * w4.y;
        acc += tanh_fast(v.z + a4.z) * w4.z;
        acc += tanh_fast(v.w + a4.w) * w4.w;
    }
#pragma unroll
    for (int off = 16; off; off >>= 1) acc += __shfl_xor_sync(0xffffffffu, acc, off);
    if (lane == 0) g_logits[b * SC + s] = acc + bms[0];
}

// ---------------------------------------------------------------------------
// softmax + weighted ctx sum + tr -> r.  grid (32 b, 4 col-groups of 128),
// 256 threads.  Softmax recomputed per col-group (cheap, deterministic).
// ---------------------------------------------------------------------------
__global__ __launch_bounds__(256) void update_kernel()
{
    __shared__ float p[SC];
    __shared__ float red[8];
    __shared__ float red2[8];
    __shared__ float4 part[8][32];

    const int b = blockIdx.x, cg = blockIdx.y, tid = threadIdx.x;

    float l = g_logits[b * SC + tid];
    float m = l;
#pragma unroll
    for (int off = 16; off; off >>= 1) m = fmaxf(m, __shfl_xor_sync(0xffffffffu, m, off));
    if ((tid & 31) == 0) red[tid >> 5] = m;
    __syncthreads();
    float mm = red[0];
#pragma unroll
    for (int i = 1; i < 8; i++) mm = fmaxf(mm, red[i]);

    float e = __expf(l - mm);
    float sZ = e;
#pragma unroll
    for (int off = 16; off; off >>= 1) sZ += __shfl_xor_sync(0xffffffffu, sZ, off);
    if ((tid & 31) == 0) red2[tid >> 5] = sZ;
    __syncthreads();
    float Z = 0.f;
#pragma unroll
    for (int i = 0; i < 8; i++) Z += red2[i];
    p[tid] = e / Z;
    __syncthreads();

    const int f4c = tid & 31;        // float4 col within group
    const int sg  = tid >> 5;        // s-group 0..7 (32 s each)
    const int col4 = cg * 32 + f4c;  // global float4 col (0..127)
    const float4* cb = (const float4*)(g_ctx + (long)b * SC * D);

    float4 acc = make_float4(0.f, 0.f, 0.f, 0.f);
#pragma unroll 8
    for (int i = 0; i < 32; i++) {
        int s = sg * 32 + i;
        float w = p[s];
        float4 v = cb[(long)s * 128 + col4];
        acc.x += w * v.x; acc.y += w * v.y; acc.z += w * v.z; acc.w += w * v.w;
    }
    part[sg][f4c] = acc;
    __syncthreads();
    if (sg == 0) {
        float4 o = part[0][f4c];
#pragma unroll
        for (int g = 1; g < 8; g++) {
            float4 q = part[g][f4c];
            o.x += q.x; o.y += q.y; o.z += q.z; o.w += q.w;
        }
        float4 t4 = ((const float4*)(g_tr + b * D))[col4];
        o.x += t4.x; o.y += t4.y; o.z += t4.z; o.w += t4.w;
        ((float4*)(g_r + b * D))[col4] = o;
    }
}

// ---------------------------------------------------------------------------
// Final: out[32,512] = r@W_rg + b_rg + qh@W_qg + b_qg
// ---------------------------------------------------------------------------
__global__ __launch_bounds__(128) void final_kernel(
    const float* __restrict__ rA, const float* __restrict__ Wrg, const float* __restrict__ brg,
    const float* __restrict__ qh, const float* __restrict__ Wqg, const float* __restrict__ bqg,
    float* __restrict__ out)
{
    __shared__ float As[16][68];
    __shared__ float Ws[64][20];

    const int ct = blockIdx.x * 16;
    const int bh = blockIdx.y * 16;
    const int tid = threadIdx.x;
    const int row = tid >> 3, cp = tid & 7;
    const int koff = (tid & 7) * 8;
    const int wk = tid >> 1, wq = (tid & 1) * 8;

    u64 acc = 0ull;

    for (int ph = 0; ph < 2; ph++) {
        const float* A = ph ? qh : rA;
        const float* W = ph ? Wqg : Wrg;
        for (int kt = 0; kt < D; kt += 64) {
            *(float4*)&As[row][koff]     = *(const float4*)&A[(bh + row) * D + kt + koff];
            *(float4*)&As[row][koff + 4] = *(const float4*)&A[(bh + row) * D + kt + koff + 4];
            *(float4*)&Ws[wk][wq]     = *(const float4*)&W[(long)(kt + wk) * D + ct + wq];
            *(float4*)&Ws[wk][wq + 4] = *(const float4*)&W[(long)(kt + wk) * D + ct + wq + 4];
            __syncthreads();
#pragma unroll
            for (int k = 0; k < 64; k++) {
                float a = As[row][k];
                u64 wv = *(const u64*)&Ws[k][cp * 2];
                acc = ffma2(pack2(a, a), wv, acc);
            }
            __syncthreads();
        }
    }

    float2 v = unpack2(acc);
    v.x += brg[ct + cp * 2]     + bqg[ct + cp * 2];
    v.y += brg[ct + cp * 2 + 1] + bqg[ct + cp * 2 + 1];
    *(float2*)&out[(bh + row) * D + ct + cp * 2] = v;
}

__global__ void zero_r_kernel()
{
    int i = blockIdx.x * blockDim.x + threadIdx.x;
    if (i < NB * D) g_r[i] = 0.f;
}

// ---------------------------------------------------------------------------
extern "C" void kernel_launch(void* const* d_in, const int* in_sizes, int n_in,
                              void* d_out, int out_size)
{
    const float* ctx_in = (const float*)d_in[0];   // [256,32,512] seq-first
    const float* q_in   = (const float*)d_in[1];   // [32,32,512] row-major M=1024
    const float* qh     = (const float*)d_in[2];   // [32,512]
    const float* img_in = (const float*)d_in[3];   // [256,32,512]
    const float* W_fc1 = (const float*)d_in[4];  const float* b_fc1 = (const float*)d_in[5];
    const float* W_fc2 = (const float*)d_in[6];  const float* b_fc2 = (const float*)d_in[7];
    const float* W_dm  = (const float*)d_in[8];  const float* b_dm  = (const float*)d_in[9];
    const float* W_rm  = (const float*)d_in[10]; const float* b_rm  = (const float*)d_in[11];
    const float* W_qm  = (const float*)d_in[12]; const float* b_qm  = (const float*)d_in[13];
    const float* W_rr  = (const float*)d_in[14]; const float* b_rr  = (const float*)d_in[15];
    const float* W_rg  = (const float*)d_in[16]; const float* b_rg  = (const float*)d_in[17];
    const float* W_qg  = (const float*)d_in[18]; const float* b_qg  = (const float*)d_in[19];
    const float* W_ms  = (const float*)d_in[20]; const float* b_ms  = (const float*)d_in[21];
    float* out = (float*)d_out;

    float *ctx, *ctxdm, *qm, *r, *tr, *rm;
    cudaGetSymbolAddress((void**)&ctx,   g_ctx);
    cudaGetSymbolAddress((void**)&ctxdm, g_ctxdm);
    cudaGetSymbolAddress((void**)&qm,    g_qm);
    cudaGetSymbolAddress((void**)&r,     g_r);
    cudaGetSymbolAddress((void**)&tr,    g_tr);
    cudaGetSymbolAddress((void**)&rm,    g_rm);

    zero_r_kernel<<<32, 512>>>();

    // ctx = context@W_fc1 + image@W_fc2 + biases   (M=8192, K=1024, 2 phases)
    sgemm_fc_kernel<<<dim3(4, 64), 512>>>(ctx_in, W_fc1, b_fc1, img_in, W_fc2, b_fc2, ctx);
    // ctxdm = ctx@W_dm (by<64)  +  qm = q@W_qm (by>=64), one launch
    sgemm_dual_kernel<<<dim3(4, 72), 512>>>(ctx, W_dm, b_dm, ctxdm,
                                            q_in, W_qm, b_qm, qm);

    for (int t = 0; t < SQ; t++) {
        gemv_kernel<<<dim3(32, 2), 256>>>(r, W_rm, b_rm, W_rr, b_rr, rm, tr);
        logits_kernel<<<dim3(32, 32), 256>>>(qm + (long)t * NB * D, W_ms, b_ms);
        update_kernel<<<dim3(32, 4), 256>>>();
    }

    final_kernel<<<dim3(32, 2), 128>>>(r, W_rg, b_rg, qh, W_qg, b_qg, out);
}